// round 4
// baseline (speedup 1.0000x reference)
#include <cuda_runtime.h>
#include <cuda_bf16.h>

// SHEmbed: out[b,c] = clip( sum_j SH_j(ray_dir[b]) * sh_data[y[b], x[b], j, c], 0, 1 )
// L=3 -> 16 basis, 3 channels. H=W=1024, B=1048576.
// Inputs: y:int32[B], x:int32[B], ray_dir:f32[B,3], sh_data:f32[H,W,16,3]
// Output: f32[B,3]
//
// R3 strategy: the random per-thread 192B gather was L1tex-wavefront-bound
// (each LDG.128 touched ~32 lines). Stage cell data through shared memory with
// COALESCED cooperative loads: consecutive lanes cover consecutive float4s of
// the block's 128 cells, so each LDG.128 touches ~6 lines instead of 32.
// Smem is padded to 13 float4s per cell -> conflict-free reads.

#define SH_W 1024
#define BLK  128
#define F4_PER_CELL 12            // 48 floats = 12 float4 = 192 B
#define F4_STRIDE   13            // padded stride (conflict-free: 20*l mod 32 distinct)

__global__ __launch_bounds__(BLK)
void SHEmbed_69406671503663_kernel(const int* __restrict__ ys,
                                   const int* __restrict__ xs,
                                   const float* __restrict__ dir,
                                   const float* __restrict__ sh,
                                   float* __restrict__ out,
                                   int n)
{
    __shared__ float4   s_coef[BLK * F4_STRIDE];   // 26624 B
    __shared__ unsigned s_cell[BLK];               // float4-index of each ray's cell

    const int tid = threadIdx.x;
    int i = blockIdx.x * BLK + tid;
    int il = i < n ? i : (n - 1);                  // clamped for loads (B divisible anyway)

    // ---- per-ray cell index ----
    unsigned cell4 = ((unsigned)ys[il] * SH_W + (unsigned)xs[il]) * F4_PER_CELL;
    s_cell[tid] = cell4;

    // ---- direction & closed-form L=3 real SH basis (reference sign convention) ----
    float dx = dir[3 * il + 0];
    float dy = dir[3 * il + 1];
    float dz = dir[3 * il + 2];
    float inv = 1.0f / (sqrtf(fmaf(dx, dx, fmaf(dy, dy, dz * dz))) + 1e-14f);
    float x = dx * inv, y = dy * inv, z = dz * inv;
    float xx = x * x, yy = y * y, zz = z * z;

    float b[16];
    b[0]  =  0.28209479177387814f;
    b[1]  = -0.4886025119029199f * y;
    b[2]  =  0.4886025119029199f * z;
    b[3]  = -0.4886025119029199f * x;
    b[4]  =  1.0925484305920792f * x * y;
    b[5]  = -1.0925484305920792f * y * z;
    b[6]  =  0.31539156525252005f * (3.0f * zz - 1.0f);
    b[7]  = -1.0925484305920792f * x * z;
    b[8]  =  0.5462742152960396f * (xx - yy);
    b[9]  = -0.5900435899266435f * y * (3.0f * xx - yy);
    b[10] =  2.890611442640554f  * x * y * z;
    b[11] = -0.4570457994644658f * y * (5.0f * zz - 1.0f);
    b[12] =  0.3731763325901154f * z * (5.0f * zz - 3.0f);
    b[13] = -0.4570457994644658f * x * (5.0f * zz - 1.0f);
    b[14] =  1.445305721320277f  * z * (xx - yy);
    b[15] = -0.5900435899266435f * x * (xx - 3.0f * yy);

    __syncthreads();

    // ---- cooperative, coalesced gather of all 128 cells (12 float4 each) ----
    // Flat float4 index F in [0, 128*12): consecutive lanes -> consecutive
    // addresses within each 192B cell -> ~2 lines per cell instead of 1/float4.
    const float4* __restrict__ sh4 = reinterpret_cast<const float4*>(sh);
    #pragma unroll
    for (int k = 0; k < F4_PER_CELL; k++) {
        int F = tid + BLK * k;             // < 1536
        int c = F / F4_PER_CELL;           // cell slot in block
        int q = F - c * F4_PER_CELL;       // float4 within cell
        s_coef[c * F4_STRIDE + q] = __ldg(sh4 + s_cell[c] + q);
    }

    __syncthreads();

    // ---- fused dot product from smem (conflict-free: stride 13 float4) ----
    const float4* __restrict__ my = &s_coef[tid * F4_STRIDE];
    float acc0 = 0.f, acc1 = 0.f, acc2 = 0.f;
    #pragma unroll
    for (int q = 0; q < F4_PER_CELL; q++) {
        float4 v = my[q];
        const int f0 = 4 * q + 0, f1 = 4 * q + 1, f2 = 4 * q + 2, f3 = 4 * q + 3;
        // flat float index f -> (j, ch) = (f/3, f%3), all compile-time
        if      (f0 % 3 == 0) acc0 = fmaf(b[f0 / 3], v.x, acc0);
        else if (f0 % 3 == 1) acc1 = fmaf(b[f0 / 3], v.x, acc1);
        else                  acc2 = fmaf(b[f0 / 3], v.x, acc2);
        if      (f1 % 3 == 0) acc0 = fmaf(b[f1 / 3], v.y, acc0);
        else if (f1 % 3 == 1) acc1 = fmaf(b[f1 / 3], v.y, acc1);
        else                  acc2 = fmaf(b[f1 / 3], v.y, acc2);
        if      (f2 % 3 == 0) acc0 = fmaf(b[f2 / 3], v.z, acc0);
        else if (f2 % 3 == 1) acc1 = fmaf(b[f2 / 3], v.z, acc1);
        else                  acc2 = fmaf(b[f2 / 3], v.z, acc2);
        if      (f3 % 3 == 0) acc0 = fmaf(b[f3 / 3], v.w, acc0);
        else if (f3 % 3 == 1) acc1 = fmaf(b[f3 / 3], v.w, acc1);
        else                  acc2 = fmaf(b[f3 / 3], v.w, acc2);
    }

    if (i < n) {
        out[3 * i + 0] = fminf(fmaxf(acc0, 0.0f), 1.0f);
        out[3 * i + 1] = fminf(fmaxf(acc1, 0.0f), 1.0f);
        out[3 * i + 2] = fminf(fmaxf(acc2, 0.0f), 1.0f);
    }
}

extern "C" void kernel_launch(void* const* d_in, const int* in_sizes, int n_in,
                              void* d_out, int out_size)
{
    const int*   ys  = (const int*)d_in[0];
    const int*   xs  = (const int*)d_in[1];
    const float* dir = (const float*)d_in[2];
    const float* sh  = (const float*)d_in[3];
    float*       out = (float*)d_out;

    int n = in_sizes[0];
    int blocks = (n + BLK - 1) / BLK;
    SHEmbed_69406671503663_kernel<<<blocks, BLK>>>(ys, xs, dir, sh, out, n);
}

// round 5
// speedup vs baseline: 1.6557x; 1.6557x over previous
#include <cuda_runtime.h>
#include <cuda_bf16.h>

// SHEmbed: out[b,c] = clip( sum_j SH_j(ray_dir[b]) * sh_data[y[b], x[b], j, c], 0, 1 )
// L=3 -> 16 basis, 3 channels. H=W=1024, B=1048576.
// Inputs: y:int32[B], x:int32[B], ray_dir:f32[B,3], sh_data:f32[H,W,16,3]
// Output: f32[B,3]
//
// R4: 4-lane cooperative gather (no smem, no barriers). Lanes 4r..4r+3 own ray
// r; lane sub-id c loads float4s {c, 4+c, 8+c} so each warp LDG.128 reads a
// 64B-consecutive chunk per cell (~12 lines/LDG vs 32 in the 1-thread/ray
// version). Partial dots reduced with 2 shfl_xor rounds.

#define SH_W 1024
#define BLK  256

// Lane sub-id C owns global flat floats f = 16k + 4C + j (k=0..2, j=0..3);
// f -> (basis j = f/3, channel = f%3), all compile-time.
template <int C>
__device__ __forceinline__ void dot_part(const float* __restrict__ b,
                                         float4 v0, float4 v1, float4 v2,
                                         float& a0, float& a1, float& a2)
{
    float vv[12] = { v0.x, v0.y, v0.z, v0.w,
                     v1.x, v1.y, v1.z, v1.w,
                     v2.x, v2.y, v2.z, v2.w };
    #pragma unroll
    for (int k = 0; k < 3; ++k) {
        #pragma unroll
        for (int j = 0; j < 4; ++j) {
            const int f  = 16 * k + 4 * C + j;
            const int jj = f / 3;
            const int ch = f % 3;
            float val = vv[4 * k + j];
            if      (ch == 0) a0 = fmaf(b[jj], val, a0);
            else if (ch == 1) a1 = fmaf(b[jj], val, a1);
            else              a2 = fmaf(b[jj], val, a2);
        }
    }
}

__global__ __launch_bounds__(BLK)
void SHEmbed_69406671503663_kernel(const int* __restrict__ ys,
                                   const int* __restrict__ xs,
                                   const float* __restrict__ dir,
                                   const float* __restrict__ sh,
                                   float* __restrict__ out,
                                   int n)
{
    const int lane = threadIdx.x & 31;
    const int gw   = blockIdx.x * (BLK / 32) + (threadIdx.x >> 5);  // global warp id
    const int c    = lane & 3;                 // sub-id within 4-lane group
    const int r    = gw * 8 + (lane >> 2);     // ray owned by this group
    const int rl   = r < n ? r : (n - 1);      // clamped for loads

    // ---- cell index (4 lanes same address -> broadcast) ----
    unsigned u = ((unsigned)ys[rl] * SH_W + (unsigned)xs[rl]) * 12u;
    const float4* __restrict__ sh4 = reinterpret_cast<const float4*>(sh);

    // ---- cooperative coef loads: per LDG, group covers 64 consecutive bytes ----
    float4 v0 = __ldg(sh4 + u + 0 + c);
    float4 v1 = __ldg(sh4 + u + 4 + c);
    float4 v2 = __ldg(sh4 + u + 8 + c);

    // ---- direction & closed-form L=3 real SH basis (reference signs) ----
    float dx = dir[3 * rl + 0];
    float dy = dir[3 * rl + 1];
    float dz = dir[3 * rl + 2];
    float inv = 1.0f / (sqrtf(fmaf(dx, dx, fmaf(dy, dy, dz * dz))) + 1e-14f);
    float x = dx * inv, y = dy * inv, z = dz * inv;
    float xx = x * x, yy = y * y, zz = z * z;

    float b[16];
    b[0]  =  0.28209479177387814f;
    b[1]  = -0.4886025119029199f * y;
    b[2]  =  0.4886025119029199f * z;
    b[3]  = -0.4886025119029199f * x;
    b[4]  =  1.0925484305920792f * x * y;
    b[5]  = -1.0925484305920792f * y * z;
    b[6]  =  0.31539156525252005f * (3.0f * zz - 1.0f);
    b[7]  = -1.0925484305920792f * x * z;
    b[8]  =  0.5462742152960396f * (xx - yy);
    b[9]  = -0.5900435899266435f * y * (3.0f * xx - yy);
    b[10] =  2.890611442640554f  * x * y * z;
    b[11] = -0.4570457994644658f * y * (5.0f * zz - 1.0f);
    b[12] =  0.3731763325901154f * z * (5.0f * zz - 3.0f);
    b[13] = -0.4570457994644658f * x * (5.0f * zz - 1.0f);
    b[14] =  1.445305721320277f  * z * (xx - yy);
    b[15] = -0.5900435899266435f * x * (xx - 3.0f * yy);

    // ---- partial dot, specialized on c ----
    float a0 = 0.f, a1 = 0.f, a2 = 0.f;
    switch (c) {
        case 0: dot_part<0>(b, v0, v1, v2, a0, a1, a2); break;
        case 1: dot_part<1>(b, v0, v1, v2, a0, a1, a2); break;
        case 2: dot_part<2>(b, v0, v1, v2, a0, a1, a2); break;
        default: dot_part<3>(b, v0, v1, v2, a0, a1, a2); break;
    }

    // ---- reduce across the 4-lane group ----
    a0 += __shfl_xor_sync(0xffffffffu, a0, 1);
    a0 += __shfl_xor_sync(0xffffffffu, a0, 2);
    a1 += __shfl_xor_sync(0xffffffffu, a1, 1);
    a1 += __shfl_xor_sync(0xffffffffu, a1, 2);
    a2 += __shfl_xor_sync(0xffffffffu, a2, 1);
    a2 += __shfl_xor_sync(0xffffffffu, a2, 2);

    // ---- coalesced store: lanes c<3 write out[3r + c] (24 consecutive floats/warp) ----
    if (r < n && c < 3) {
        float res = (c == 0) ? a0 : ((c == 1) ? a1 : a2);
        out[3 * r + c] = fminf(fmaxf(res, 0.0f), 1.0f);
    }
}

extern "C" void kernel_launch(void* const* d_in, const int* in_sizes, int n_in,
                              void* d_out, int out_size)
{
    const int*   ys  = (const int*)d_in[0];
    const int*   xs  = (const int*)d_in[1];
    const float* dir = (const float*)d_in[2];
    const float* sh  = (const float*)d_in[3];
    float*       out = (float*)d_out;

    int n = in_sizes[0];
    int warps  = (n + 7) / 8;                    // 8 rays per warp
    int blocks = (warps + (BLK / 32) - 1) / (BLK / 32);
    SHEmbed_69406671503663_kernel<<<blocks, BLK>>>(ys, xs, dir, sh, out, n);
}

// round 8
// speedup vs baseline: 1.9856x; 1.1992x over previous
#include <cuda_runtime.h>
#include <cuda_bf16.h>

// SHEmbed: out[b,c] = clip( sum_j SH_j(ray_dir[b]) * sh_data[y[b], x[b], j, c], 0, 1 )
// L=3 -> 16 basis, 3 channels. H=W=1024, B=1048576.
// Inputs: y:int32[B], x:int32[B], ray_dir:f32[B,3], sh_data:f32[H,W,16,3]
// Output: f32[B,3]
//
// R6: 2-lane cooperative gather with Blackwell 256-bit loads.
// ptxas only allows L2::evict_last on .v8.b32/.v4.b64 (256-bit) loads, so the
// pair scheme kills two birds: legal evict hint (pin ~121MB unique coef set in
// 126MB L2) + half the LDG instructions. Streams (y/x/dir/out) use .cs
// (evict-first) so they don't churn L2.

#define SH_W 1024
#define BLK  256

// 256-bit load with L2 evict_last, 32B-aligned.
__device__ __forceinline__ void ldg256_keep(const float* __restrict__ p, float* v)
{
    unsigned r0, r1, r2, r3, r4, r5, r6, r7;
    asm("ld.global.nc.L2::evict_last.v8.b32 {%0,%1,%2,%3,%4,%5,%6,%7}, [%8];"
        : "=r"(r0), "=r"(r1), "=r"(r2), "=r"(r3),
          "=r"(r4), "=r"(r5), "=r"(r6), "=r"(r7)
        : "l"(p));
    v[0] = __uint_as_float(r0); v[1] = __uint_as_float(r1);
    v[2] = __uint_as_float(r2); v[3] = __uint_as_float(r3);
    v[4] = __uint_as_float(r4); v[5] = __uint_as_float(r5);
    v[6] = __uint_as_float(r6); v[7] = __uint_as_float(r7);
}

// Lane sub-id C (0/1) owns flat floats f = 16k + 8C + j (k=0..2, j=0..7);
// f -> (basis jj = f/3, channel = f%3), all compile-time.
template <int C>
__device__ __forceinline__ void dot_part(const float* __restrict__ b,
                                         const float* __restrict__ vv, // [24]
                                         float& a0, float& a1, float& a2)
{
    #pragma unroll
    for (int k = 0; k < 3; ++k) {
        #pragma unroll
        for (int j = 0; j < 8; ++j) {
            const int f  = 16 * k + 8 * C + j;
            const int jj = f / 3;
            const int ch = f % 3;
            float val = vv[8 * k + j];
            if      (ch == 0) a0 = fmaf(b[jj], val, a0);
            else if (ch == 1) a1 = fmaf(b[jj], val, a1);
            else              a2 = fmaf(b[jj], val, a2);
        }
    }
}

__global__ __launch_bounds__(BLK)
void SHEmbed_69406671503663_kernel(const int* __restrict__ ys,
                                   const int* __restrict__ xs,
                                   const float* __restrict__ dir,
                                   const float* __restrict__ sh,
                                   float* __restrict__ out,
                                   int n)
{
    const int lane = threadIdx.x & 31;
    const int gw   = blockIdx.x * (BLK / 32) + (threadIdx.x >> 5);  // global warp id
    const int c    = lane & 1;                  // sub-id within lane pair
    const int r    = gw * 16 + (lane >> 1);     // ray owned by this pair
    const int rl   = r < n ? r : (n - 1);       // clamped for loads

    // ---- cell base (streaming index loads; pair -> broadcast) ----
    unsigned u = ((unsigned)__ldcs(ys + rl) * SH_W + (unsigned)__ldcs(xs + rl)) * 48u;
    const float* __restrict__ base = sh + u + c * 8;   // 32B-aligned

    // ---- cooperative coef loads: 3 x LDG.256 per lane, pair covers 192B ----
    float vv[24];
    ldg256_keep(base +  0, vv +  0);
    ldg256_keep(base + 16, vv +  8);
    ldg256_keep(base + 32, vv + 16);

    // ---- direction (streaming) & closed-form L=3 real SH basis ----
    float dx = __ldcs(dir + 3 * rl + 0);
    float dy = __ldcs(dir + 3 * rl + 1);
    float dz = __ldcs(dir + 3 * rl + 2);
    float inv = 1.0f / (sqrtf(fmaf(dx, dx, fmaf(dy, dy, dz * dz))) + 1e-14f);
    float x = dx * inv, y = dy * inv, z = dz * inv;
    float xx = x * x, yy = y * y, zz = z * z;

    float b[16];
    b[0]  =  0.28209479177387814f;
    b[1]  = -0.4886025119029199f * y;
    b[2]  =  0.4886025119029199f * z;
    b[3]  = -0.4886025119029199f * x;
    b[4]  =  1.0925484305920792f * x * y;
    b[5]  = -1.0925484305920792f * y * z;
    b[6]  =  0.31539156525252005f * (3.0f * zz - 1.0f);
    b[7]  = -1.0925484305920792f * x * z;
    b[8]  =  0.5462742152960396f * (xx - yy);
    b[9]  = -0.5900435899266435f * y * (3.0f * xx - yy);
    b[10] =  2.890611442640554f  * x * y * z;
    b[11] = -0.4570457994644658f * y * (5.0f * zz - 1.0f);
    b[12] =  0.3731763325901154f * z * (5.0f * zz - 3.0f);
    b[13] = -0.4570457994644658f * x * (5.0f * zz - 1.0f);
    b[14] =  1.445305721320277f  * z * (xx - yy);
    b[15] = -0.5900435899266435f * x * (xx - 3.0f * yy);

    // ---- partial dot, specialized on c ----
    float a0 = 0.f, a1 = 0.f, a2 = 0.f;
    if (c == 0) dot_part<0>(b, vv, a0, a1, a2);
    else        dot_part<1>(b, vv, a0, a1, a2);

    // ---- reduce across the lane pair ----
    a0 += __shfl_xor_sync(0xffffffffu, a0, 1);
    a1 += __shfl_xor_sync(0xffffffffu, a1, 1);
    a2 += __shfl_xor_sync(0xffffffffu, a2, 1);

    // ---- streaming store: even lane of each pair writes 3 floats ----
    if (r < n && c == 0) {
        __stcs(out + 3 * r + 0, fminf(fmaxf(a0, 0.0f), 1.0f));
        __stcs(out + 3 * r + 1, fminf(fmaxf(a1, 0.0f), 1.0f));
        __stcs(out + 3 * r + 2, fminf(fmaxf(a2, 0.0f), 1.0f));
    }
}

extern "C" void kernel_launch(void* const* d_in, const int* in_sizes, int n_in,
                              void* d_out, int out_size)
{
    const int*   ys  = (const int*)d_in[0];
    const int*   xs  = (const int*)d_in[1];
    const float* dir = (const float*)d_in[2];
    const float* sh  = (const float*)d_in[3];
    float*       out = (float*)d_out;

    int n = in_sizes[0];
    int warps  = (n + 15) / 16;                  // 16 rays per warp
    int blocks = (warps + (BLK / 32) - 1) / (BLK / 32);
    SHEmbed_69406671503663_kernel<<<blocks, BLK>>>(ys, xs, dir, sh, out, n);
}